// round 16
// baseline (speedup 1.0000x reference)
#include <cuda_runtime.h>
#include <cuda_bf16.h>

#define NU 339
#define NI 5825
#define NN 6164          // NU + NI
#define BB 32768
#define SS 20
#define DD 128
#define FF 8

// Scratch (device globals: allocation-free per harness rules)
__device__ float g_adjx[NN * DD];                  // 3.2 MB
__device__ float g_AX1[NN * 2 * DD];               // 6.3 MB (L2-resident)
__device__ float g_t2[(size_t)BB * 2 * 256];       // 67 MB

// ---- packed f32x2 helpers (Blackwell FFMA2; exact per-lane fma.rn) --------
__device__ __forceinline__ unsigned long long pk2(float x, float y) {
    unsigned long long r;
    asm("mov.b64 %0, {%1, %2};" : "=l"(r) : "f"(x), "f"(y));
    return r;
}
__device__ __forceinline__ float2 upk2(unsigned long long v) {
    float2 f;
    asm("mov.b64 {%0, %1}, %2;" : "=f"(f.x), "=f"(f.y) : "l"(v));
    return f;
}
__device__ __forceinline__ unsigned long long fma2_(unsigned long long a,
    unsigned long long b, unsigned long long c) {
    unsigned long long d;
    asm("fma.rn.f32x2 %0, %1, %2, %3;" : "=l"(d) : "l"(a), "l"(b), "l"(c));
    return d;
}

// ---------------------------------------------------------------------------
// Kernel A: adj_x = l2norm(user_infos@Wu + bu) ++ l2norm(item_infos@Wi + bi)
// ---------------------------------------------------------------------------
__global__ __launch_bounds__(DD) void adjx_kernel(
    const float* __restrict__ user_infos, const float* __restrict__ item_infos,
    const float* __restrict__ Wu, const float* __restrict__ bu,
    const float* __restrict__ Wi, const float* __restrict__ bi)
{
    int r = blockIdx.x;
    int d = threadIdx.x;
    const float* feat;
    const float* W;
    const float* bv;
    if (r < NU) { feat = user_infos + r * FF;        W = Wu; bv = bu; }
    else        { feat = item_infos + (r - NU) * FF; W = Wi; bv = bi; }

    float acc = bv[d];
#pragma unroll
    for (int f = 0; f < FF; f++) acc = fmaf(feat[f], W[f * DD + d], acc);

    __shared__ float red[4];
    float sq = acc * acc;
#pragma unroll
    for (int o = 16; o > 0; o >>= 1) sq += __shfl_xor_sync(0xffffffffu, sq, o);
    if ((threadIdx.x & 31) == 0) red[threadIdx.x >> 5] = sq;
    __syncthreads();
    float tot = red[0] + red[1] + red[2] + red[3];
    float nrm = fmaxf(sqrtf(tot), 1e-12f);
    g_adjx[r * DD + d] = acc / nrm;
}

// ---------------------------------------------------------------------------
// Kernel B: AX1 = adjx @ W1   (NN x 256, K=128).  NO bias (b1 added in mix).
// ---------------------------------------------------------------------------
__global__ __launch_bounds__(256) void ax1_kernel(const float* __restrict__ W1)
{
    __shared__ float sx[16][128];
    const int tid = threadIdx.x;
    const int r0 = blockIdx.x * 16;

    for (int id = tid; id < 512; id += 256) {
        int r = id >> 5, q = id & 31;
        float4 v = (r0 + r < NN)
            ? *(const float4*)&g_adjx[(long)(r0 + r) * DD + q * 4]
            : make_float4(0.f, 0.f, 0.f, 0.f);
        *(float4*)&sx[r][q * 4] = v;
    }
    __syncthreads();

    float acc[16];
#pragma unroll
    for (int i = 0; i < 16; i++) acc[i] = 0.f;

    for (int k = 0; k < DD; k++) {
        float w = __ldg(&W1[(long)k * 256 + tid]);
#pragma unroll
        for (int i = 0; i < 16; i++) acc[i] = fmaf(sx[i][k], w, acc[i]);
    }

#pragma unroll
    for (int i = 0; i < 16; i++)
        if (r0 + i < NN) g_AX1[(long)(r0 + i) * 256 + tid] = acc[i];
}

// ---------------------------------------------------------------------------
// Kernel C: mix. 1 element per block, 256 threads, thread owns ONE column.
// Low regs (~60) -> 4 blocks/SM (32 warps). AX1 prefetch (coalesced, MLP=20)
// issued BEFORE the scattered adj gather so the two overlap. adj reads in the
// compute loop are warp-broadcast (lane-invariant).
//   h1[i][c] = relu(b1[c] + sum_j sub_adj[i][j] * AX1[sid[j]][c])
//   t2[r][c] = sum_i sub_adj[root_r][i] * h1[i][c]
// H[p] packs rows (2p, 2p+1) for this thread's column.
// ---------------------------------------------------------------------------
__global__ __launch_bounds__(256) void mix_kernel(
    const int* __restrict__ sample_ids,
    const int* __restrict__ roots,
    const float* __restrict__ adj,
    const float* __restrict__ b1)
{
    __shared__ int   s_sid[SS];
    __shared__ float s_adjT[SS][24];   // s_adjT[j][i] = sub_adj[i][j]
    __shared__ int   s_rt[2];

    const int tid = threadIdx.x;
    const int b = blockIdx.x;

    if (tid < SS) s_sid[tid] = sample_ids[b * SS + tid];
    if (tid >= 32 && tid < 34) s_rt[tid - 32] = roots[b * 2 + (tid - 32)];
    __syncthreads();

    // coalesced AX1 prefetch: 20 independent 128B-per-warp loads in flight
    float ax[SS];
#pragma unroll
    for (int j = 0; j < SS; j++)
        ax[j] = __ldg(&g_AX1[(long)s_sid[j] * 256 + tid]);

    // scattered adj gather (overlaps the AX1 loads above)
    for (int id = tid; id < SS * SS; id += 256) {
        int jj = id / SS, ii = id % SS;
        s_adjT[jj][ii] = __ldg(&adj[(long)s_sid[ii] * NN + s_sid[jj]]);
    }
    __syncthreads();

    const float bc = __ldg(&b1[tid]);
    unsigned long long H[10];
    {
        unsigned long long bcp = pk2(bc, bc);
#pragma unroll
        for (int p = 0; p < 10; p++) H[p] = bcp;
    }

#pragma unroll
    for (int j = 0; j < SS; j++) {
        ulonglong2 A0 = *(const ulonglong2*)&s_adjT[j][0];    // rows 0..3
        ulonglong2 A1 = *(const ulonglong2*)&s_adjT[j][4];    // rows 4..7
        ulonglong2 A2 = *(const ulonglong2*)&s_adjT[j][8];    // rows 8..11
        ulonglong2 A3 = *(const ulonglong2*)&s_adjT[j][12];   // rows 12..15
        ulonglong2 A4 = *(const ulonglong2*)&s_adjT[j][16];   // rows 16..19
        unsigned long long axp = pk2(ax[j], ax[j]);
        H[0] = fma2_(A0.x, axp, H[0]);
        H[1] = fma2_(A0.y, axp, H[1]);
        H[2] = fma2_(A1.x, axp, H[2]);
        H[3] = fma2_(A1.y, axp, H[3]);
        H[4] = fma2_(A2.x, axp, H[4]);
        H[5] = fma2_(A2.y, axp, H[5]);
        H[6] = fma2_(A3.x, axp, H[6]);
        H[7] = fma2_(A3.y, axp, H[7]);
        H[8] = fma2_(A4.x, axp, H[8]);
        H[9] = fma2_(A4.y, axp, H[9]);
    }

    const int r0 = s_rt[0], r1 = s_rt[1];
    float t0 = 0.f, t1 = 0.f;
#pragma unroll
    for (int p = 0; p < 10; p++) {
        float2 h = upk2(H[p]);
        float ha = fmaxf(h.x, 0.f);     // row 2p
        float hb = fmaxf(h.y, 0.f);     // row 2p+1
        float wa0 = s_adjT[2 * p][r0], wb0 = s_adjT[2 * p + 1][r0];
        float wa1 = s_adjT[2 * p][r1], wb1 = s_adjT[2 * p + 1][r1];
        t0 = fmaf(wa0, ha, t0); t0 = fmaf(wb0, hb, t0);
        t1 = fmaf(wa1, ha, t1); t1 = fmaf(wb1, hb, t1);
    }

    const long base = (long)b * 512;
    g_t2[base + tid]       = t0;
    g_t2[base + 256 + tid] = t1;
}

// ---------------------------------------------------------------------------
// Kernel D: tail, 32 elements per block, 256 threads, 96KB dynamic smem.
// Double-buffered weight staging (validated R14). Unchanged.
// ---------------------------------------------------------------------------
__global__ __launch_bounds__(256) void tail_kernel(
    const int*   __restrict__ user_idx,
    const int*   __restrict__ item_idx,
    const float* __restrict__ uid_emb,
    const float* __restrict__ sid_emb,
    const float* __restrict__ W2, const float* __restrict__ b2,
    const float* __restrict__ mW0, const float* __restrict__ mb0,
    const float* __restrict__ mW1, const float* __restrict__ mb1,
    const float* __restrict__ mW2, const float* __restrict__ mb2,
    float* __restrict__ out)
{
    extern __shared__ float dsm[];
    float* bufA = dsm;            // 16384 floats
    float* wb0  = dsm + 16384;    // 4096 floats
    float* wb1  = dsm + 20480;    // 4096 floats

    const int tid = threadIdx.x;
    const int tx = tid & 31, ty = tid >> 5;
    const int b0 = blockIdx.x * 32;
    const int sk = tid >> 5;          // staging row-group (= ty)
    const int sq4 = tid & 31;         // staging quad col

    // load t2 for 32 elements (16384 floats, contiguous)
    {
        const float4* src = (const float4*)(g_t2 + (long)b0 * 512);
        for (int id = tid; id < 4096; id += 256) ((float4*)bufA)[id] = src[id];
    }

    // stage W2 chunk 0 into wb0 (rows 0..31 x 128)
#pragma unroll
    for (int p = 0; p < 4; p++) {
        int k = p * 8 + sk;
        *(float4*)&wb0[k * 128 + sq4 * 4] =
            *(const float4*)&W2[(long)k * 128 + sq4 * 4];
    }
    __syncthreads();

    // ---- ft = t2 @ W2: 64 rows (er = ty+8s, s<8) x 128 cols, K=256 ----
    unsigned long long f2[8][2];
#pragma unroll
    for (int s = 0; s < 8; s++) { f2[s][0] = 0ULL; f2[s][1] = 0ULL; }

#pragma unroll
    for (int ch = 0; ch < 8; ch++) {
        float* wcur = (ch & 1) ? wb1 : wb0;
        float* wnxt = (ch & 1) ? wb0 : wb1;
        const int c0 = ch * 32;
        float4 pre[4];
        if (ch < 7) {
#pragma unroll
            for (int p = 0; p < 4; p++) {
                int k = p * 8 + sk;
                pre[p] = *(const float4*)&W2[(long)(c0 + 32 + k) * 128 + sq4 * 4];
            }
        }
#pragma unroll
        for (int kk4 = 0; kk4 < 8; kk4++) {
            float4 tv[8];
#pragma unroll
            for (int s = 0; s < 8; s++)
                tv[s] = *(const float4*)&bufA[(ty + 8 * s) * 256 + c0 + kk4 * 4];
#pragma unroll
            for (int u = 0; u < 4; u++) {
                ulonglong2 wp = *(const ulonglong2*)&wcur[(kk4 * 4 + u) * 128 + tx * 4];
#pragma unroll
                for (int s = 0; s < 8; s++) {
                    float t = ((const float*)&tv[s])[u];
                    unsigned long long tb = pk2(t, t);
                    f2[s][0] = fma2_(tb, wp.x, f2[s][0]);
                    f2[s][1] = fma2_(tb, wp.y, f2[s][1]);
                }
            }
        }
        if (ch < 7) {
#pragma unroll
            for (int p = 0; p < 4; p++) {
                int k = p * 8 + sk;
                *(float4*)&wnxt[k * 128 + sq4 * 4] = pre[p];
            }
        }
        __syncthreads();
    }

    // unpack + merge with id_vec: x[e][r*128+d] = 0.6*emb + 0.4*relu(f + b2)
    float f[8][4];
#pragma unroll
    for (int s = 0; s < 8; s++) {
        float2 p0 = upk2(f2[s][0]);
        float2 p1 = upk2(f2[s][1]);
        f[s][0] = p0.x; f[s][1] = p0.y; f[s][2] = p1.x; f[s][3] = p1.y;
    }
    {
        float4 bv = *(const float4*)&b2[tx * 4];
#pragma unroll
        for (int s = 0; s < 8; s++) {
            int er = ty + 8 * s;
            int e = er >> 1, r = er & 1;
            const float* emb = (r == 0)
                ? &uid_emb[(long)__ldg(&user_idx[b0 + e]) * DD]
                : &sid_emb[(long)__ldg(&item_idx[b0 + e]) * DD];
            float4 idv = __ldg((const float4*)&emb[tx * 4]);
            f[s][0] = 0.6f * idv.x + 0.4f * fmaxf(f[s][0] + bv.x, 0.f);
            f[s][1] = 0.6f * idv.y + 0.4f * fmaxf(f[s][1] + bv.y, 0.f);
            f[s][2] = 0.6f * idv.z + 0.4f * fmaxf(f[s][2] + bv.z, 0.f);
            f[s][3] = 0.6f * idv.w + 0.4f * fmaxf(f[s][3] + bv.w, 0.f);
        }
    }
    __syncthreads();   // all t2 reads done; safe to overwrite bufA[0:8192)
#pragma unroll
    for (int s = 0; s < 8; s++) {
        int er = ty + 8 * s;
        int e = er >> 1, r = er & 1;
        *(float4*)&bufA[e * 256 + r * 128 + tx * 4] = *(float4*)&f[s][0];
    }
    // stage mW0 chunk 0 into wb0
#pragma unroll
    for (int p = 0; p < 4; p++) {
        int k = p * 8 + sk;
        *(float4*)&wb0[k * 128 + sq4 * 4] =
            *(const float4*)&mW0[(long)k * 128 + sq4 * 4];
    }
    __syncthreads();

    // ---- MLP0: y1 = relu(x @ mW0 + mb0): elems e = ty+8s (s<4), cols tx*4 ----
    unsigned long long g2[4][2];
#pragma unroll
    for (int s = 0; s < 4; s++) { g2[s][0] = 0ULL; g2[s][1] = 0ULL; }

#pragma unroll
    for (int ch = 0; ch < 8; ch++) {
        float* wcur = (ch & 1) ? wb1 : wb0;
        float* wnxt = (ch & 1) ? wb0 : wb1;
        const int c0 = ch * 32;
        float4 pre[4];
        if (ch < 7) {
#pragma unroll
            for (int p = 0; p < 4; p++) {
                int k = p * 8 + sk;
                pre[p] = *(const float4*)&mW0[(long)(c0 + 32 + k) * 128 + sq4 * 4];
            }
        }
#pragma unroll
        for (int kk4 = 0; kk4 < 8; kk4++) {
            float4 xv[4];
#pragma unroll
            for (int s = 0; s < 4; s++)
                xv[s] = *(const float4*)&bufA[(ty + 8 * s) * 256 + c0 + kk4 * 4];
#pragma unroll
            for (int u = 0; u < 4; u++) {
                ulonglong2 wp = *(const ulonglong2*)&wcur[(kk4 * 4 + u) * 128 + tx * 4];
#pragma unroll
                for (int s = 0; s < 4; s++) {
                    float x = ((const float*)&xv[s])[u];
                    unsigned long long xb = pk2(x, x);
                    g2[s][0] = fma2_(xb, wp.x, g2[s][0]);
                    g2[s][1] = fma2_(xb, wp.y, g2[s][1]);
                }
            }
        }
        if (ch < 7) {
#pragma unroll
            for (int p = 0; p < 4; p++) {
                int k = p * 8 + sk;
                *(float4*)&wnxt[k * 128 + sq4 * 4] = pre[p];
            }
        }
        __syncthreads();
    }
    {
        float4 bv = __ldg((const float4*)&mb0[tx * 4]);
#pragma unroll
        for (int s = 0; s < 4; s++) {
            int e = ty + 8 * s;
            float2 p0 = upk2(g2[s][0]);
            float2 p1 = upk2(g2[s][1]);
            float4 y;
            y.x = fmaxf(p0.x + bv.x, 0.f); y.y = fmaxf(p0.y + bv.y, 0.f);
            y.z = fmaxf(p1.x + bv.z, 0.f); y.w = fmaxf(p1.y + bv.w, 0.f);
            *(float4*)&bufA[8192 + e * 128 + tx * 4] = y;   // y1[e][128]
        }
    }
    // stage mW1 chunk 0 (rows 0..63 x 64 = 4096 floats) into wb0
#pragma unroll
    for (int p = 0; p < 4; p++) {
        int id = p * 256 + tid;
        int k = id >> 4, dq = id & 15;
        *(float4*)&wb0[k * 64 + dq * 4] =
            *(const float4*)&mW1[(long)k * 64 + dq * 4];
    }
    __syncthreads();

    // ---- MLP1: y2 = relu(y1 @ mW1 + mb1): elems e = ty+8s (s<4), cols tx*2 ----
    {
        const int oo = tx * 2;
        unsigned long long a2[4];
#pragma unroll
        for (int s = 0; s < 4; s++) a2[s] = 0ULL;
#pragma unroll
        for (int ch = 0; ch < 2; ch++) {
            float* wcur = ch ? wb1 : wb0;
            const int c0 = ch * 64;
            float4 pre[4];
            if (ch == 0) {
#pragma unroll
                for (int p = 0; p < 4; p++) {
                    int id = p * 256 + tid;
                    int k = id >> 4, dq = id & 15;
                    pre[p] = *(const float4*)&mW1[(long)(64 + k) * 64 + dq * 4];
                }
            }
#pragma unroll
            for (int kk4 = 0; kk4 < 16; kk4++) {
                float4 yv[4];
#pragma unroll
                for (int s = 0; s < 4; s++)
                    yv[s] = *(const float4*)&bufA[8192 + (ty + 8 * s) * 128 + c0 + kk4 * 4];
#pragma unroll
                for (int u = 0; u < 4; u++) {
                    unsigned long long wp =
                        *(const unsigned long long*)&wcur[(kk4 * 4 + u) * 64 + oo];
#pragma unroll
                    for (int s = 0; s < 4; s++) {
                        float y = ((const float*)&yv[s])[u];
                        a2[s] = fma2_(pk2(y, y), wp, a2[s]);
                    }
                }
            }
            if (ch == 0) {
#pragma unroll
                for (int p = 0; p < 4; p++) {
                    int id = p * 256 + tid;
                    int k = id >> 4, dq = id & 15;
                    *(float4*)&wb1[k * 64 + dq * 4] = pre[p];
                }
            }
            __syncthreads();
        }
        float2 bv = __ldg((const float2*)&mb1[oo]);
#pragma unroll
        for (int s = 0; s < 4; s++) {
            int e = ty + 8 * s;
            float2 av = upk2(a2[s]);
            bufA[12288 + e * 64 + oo]     = fmaxf(av.x + bv.x, 0.f);
            bufA[12288 + e * 64 + oo + 1] = fmaxf(av.y + bv.y, 0.f);
        }
    }
    __syncthreads();

    // ---- MLP2: warp ty handles elements ty+8s (s<4) ----
    {
        float wlo = __ldg(&mW2[tx]);
        float whi = __ldg(&mW2[32 + tx]);
        float bias = __ldg(&mb2[0]);
#pragma unroll
        for (int s = 0; s < 4; s++) {
            int e = ty + 8 * s;
            float p = bufA[12288 + e * 64 + tx] * wlo +
                      bufA[12288 + e * 64 + 32 + tx] * whi;
#pragma unroll
            for (int o = 16; o > 0; o >>= 1)
                p += __shfl_xor_sync(0xffffffffu, p, o);
            if (tx == 0) out[b0 + e] = fmaxf(p + bias, 0.f);
        }
    }
}

// ---------------------------------------------------------------------------
extern "C" void kernel_launch(void* const* d_in, const int* in_sizes, int n_in,
                              void* d_out, int out_size)
{
    const int*   user_indexes = (const int*)  d_in[0];
    const int*   item_indexes = (const int*)  d_in[1];
    const int*   sample_ids   = (const int*)  d_in[2];
    const int*   roots        = (const int*)  d_in[3];
    const float* user_infos   = (const float*)d_in[4];
    const float* item_infos   = (const float*)d_in[5];
    const float* adj_matrix   = (const float*)d_in[6];
    const float* uid_emb      = (const float*)d_in[7];
    const float* sid_emb      = (const float*)d_in[8];
    const float* Wu           = (const float*)d_in[9];
    const float* bu           = (const float*)d_in[10];
    const float* Wi           = (const float*)d_in[11];
    const float* bi           = (const float*)d_in[12];
    const float* W1           = (const float*)d_in[13];
    const float* b1           = (const float*)d_in[14];
    const float* W2           = (const float*)d_in[15];
    const float* b2           = (const float*)d_in[16];
    const float* mW0          = (const float*)d_in[17];
    const float* mb0          = (const float*)d_in[18];
    const float* mW1          = (const float*)d_in[19];
    const float* mb1          = (const float*)d_in[20];
    const float* mW2          = (const float*)d_in[21];
    const float* mb2          = (const float*)d_in[22];
    float* out = (float*)d_out;

    const int TAIL_SMEM = 24576 * sizeof(float);   // 96 KB
    cudaFuncSetAttribute(tail_kernel,
                         cudaFuncAttributeMaxDynamicSharedMemorySize, TAIL_SMEM);

    adjx_kernel<<<NN, DD>>>(user_infos, item_infos, Wu, bu, Wi, bi);
    ax1_kernel<<<(NN + 15) / 16, 256>>>(W1);
    mix_kernel<<<BB, 256>>>(sample_ids, roots, adj_matrix, b1);
    tail_kernel<<<BB / 32, 256, TAIL_SMEM>>>(user_indexes, item_indexes,
                                             uid_emb, sid_emb,
                                             W2, b2, mW0, mb0, mW1, mb1,
                                             mW2, mb2, out);
}